// round 1
// baseline (speedup 1.0000x reference)
#include <cuda_runtime.h>
#include <math_constants.h>

// Problem constants
#define Bq 4
#define Hq 16
#define Sq 2048
#define Dq 128

// Tiling
#define BM 64
#define BN 64
#define NTHREADS 256

// Smem strides (floats), padded, 16B-aligned rows
#define QS_STRIDE 132   // 64 rows x 128 cols (+4 pad)
#define KS_STRIDE 68    // 128 rows (k) x 64 cols (t) (+4 pad)  -- K transposed
#define VS_STRIDE 132   // 64 rows x 128 cols (+4 pad)
#define PS_STRIDE 68    // 64 rows x 64 cols (+4 pad)

#define SMEM_FLOATS (BM*QS_STRIDE + Dq*KS_STRIDE + BN*VS_STRIDE + BM*PS_STRIDE)

#define LOG2E 1.4426950408889634f

struct F4 { float f[4]; };

static __device__ __forceinline__ F4 ldf4(const float* p) {
    float4 t = *(const float4*)p;
    F4 r; r.f[0] = t.x; r.f[1] = t.y; r.f[2] = t.z; r.f[3] = t.w;
    return r;
}

__global__ __launch_bounds__(NTHREADS, 1)
void attn_fp32_kernel(const float* __restrict__ q,
                      const float* __restrict__ k,
                      const float* __restrict__ v,
                      const float* __restrict__ scale,
                      float* __restrict__ out)
{
    extern __shared__ float sm[];
    float* Qs = sm;                          // [64][132]
    float* Ks = Qs + BM * QS_STRIDE;         // [128][68]  (transposed: Ks[d][t])
    float* Vs = Ks + Dq * KS_STRIDE;         // [64][132]
    float* Ps = Vs + BN * VS_STRIDE;         // [64][68]

    const int tid = threadIdx.x;
    const int tx  = tid & 15;    // 0..15 : S-tile column group / O column group
    const int ty  = tid >> 4;    // 0..15 : S-tile row group
    const int ty4 = ty * 4;

    const int tile = blockIdx.x;   // query tile (0..31)
    const int bh   = blockIdx.y;   // head-batch (0..63)

    const size_t base = (size_t)bh * Sq * Dq;
    const float* Qg = q + base + (size_t)tile * BM * Dq;
    const float* Kg = k + base;
    const float* Vg = v + base;
    float*       Og = out + base + (size_t)tile * BM * Dq;
    const float  sc = scale[bh];

    // ---- Load Q tile once (row-major, coalesced) ----
    #pragma unroll
    for (int c = tid; c < BM * Dq / 4; c += NTHREADS) {
        int r  = c >> 5;        // 32 float4 per row
        int k4 = c & 31;
        float4 g = *(const float4*)(Qg + (size_t)r * Dq + k4 * 4);
        *(float4*)&Qs[r * QS_STRIDE + k4 * 4] = g;
    }

    // ---- Accumulators ----
    float o[4][8];
    float mrow[4], lrow[4];
    #pragma unroll
    for (int i = 0; i < 4; i++) {
        mrow[i] = -CUDART_INF_F;
        lrow[i] = 0.f;
        #pragma unroll
        for (int c = 0; c < 8; c++) o[i][c] = 0.f;
    }

    for (int n = 0; n < Sq / BN; ++n) {
        // ---- Load K tile TRANSPOSED into Ks[d][t] ----
        #pragma unroll
        for (int c = tid; c < BN * Dq / 4; c += NTHREADS) {
            int t  = c & 63;     // consecutive lanes -> consecutive t -> conflict-free STS
            int k4 = c >> 6;
            float4 g = *(const float4*)(Kg + (size_t)(n * BN + t) * Dq + k4 * 4);
            Ks[(k4 * 4 + 0) * KS_STRIDE + t] = g.x;
            Ks[(k4 * 4 + 1) * KS_STRIDE + t] = g.y;
            Ks[(k4 * 4 + 2) * KS_STRIDE + t] = g.z;
            Ks[(k4 * 4 + 3) * KS_STRIDE + t] = g.w;
        }
        // ---- Load V tile row-major (coalesced) ----
        #pragma unroll
        for (int c = tid; c < BN * Dq / 4; c += NTHREADS) {
            int t  = c >> 5;
            int c4 = c & 31;
            float4 g = *(const float4*)(Vg + (size_t)(n * BN + t) * Dq + c4 * 4);
            *(float4*)&Vs[t * VS_STRIDE + c4 * 4] = g;
        }
        __syncthreads();

        // ---- S = Q @ K^T  (4x4 microtile per thread) ----
        float acc[4][4];
        #pragma unroll
        for (int i = 0; i < 4; i++)
            #pragma unroll
            for (int j = 0; j < 4; j++) acc[i][j] = 0.f;

        #pragma unroll 4
        for (int k4 = 0; k4 < Dq / 4; ++k4) {
            F4 a[4], b[4];
            #pragma unroll
            for (int i = 0; i < 4; i++)
                a[i] = ldf4(&Qs[(ty4 + i) * QS_STRIDE + k4 * 4]);   // same-ty lanes broadcast
            #pragma unroll
            for (int kk = 0; kk < 4; kk++)
                b[kk] = ldf4(&Ks[(k4 * 4 + kk) * KS_STRIDE + tx * 4]); // consecutive, conflict-free
            #pragma unroll
            for (int i = 0; i < 4; i++)
                #pragma unroll
                for (int j = 0; j < 4; j++)
                    #pragma unroll
                    for (int kk = 0; kk < 4; kk++)
                        acc[i][j] += a[i].f[kk] * b[kk].f[j];
        }

        // ---- Online softmax (row = ty4+i, spread across 16 lanes of a half-warp) ----
        #pragma unroll
        for (int i = 0; i < 4; i++) {
            float l0 = acc[i][0] * sc;
            float l1 = acc[i][1] * sc;
            float l2 = acc[i][2] * sc;
            float l3 = acc[i][3] * sc;
            float rmax = fmaxf(fmaxf(l0, l1), fmaxf(l2, l3));
            #pragma unroll
            for (int off = 8; off; off >>= 1)
                rmax = fmaxf(rmax, __shfl_xor_sync(0xffffffffu, rmax, off));
            float mnew = fmaxf(mrow[i], rmax);

            float p0 = exp2f((l0 - mnew) * LOG2E);
            float p1 = exp2f((l1 - mnew) * LOG2E);
            float p2 = exp2f((l2 - mnew) * LOG2E);
            float p3 = exp2f((l3 - mnew) * LOG2E);
            float rsum = (p0 + p1) + (p2 + p3);
            #pragma unroll
            for (int off = 8; off; off >>= 1)
                rsum += __shfl_xor_sync(0xffffffffu, rsum, off);

            float alpha = exp2f((mrow[i] - mnew) * LOG2E);
            mrow[i] = mnew;
            lrow[i] = lrow[i] * alpha + rsum;
            #pragma unroll
            for (int c = 0; c < 8; c++) o[i][c] *= alpha;

            float4 pv;
            pv.x = p0; pv.y = p1; pv.z = p2; pv.w = p3;
            *(float4*)&Ps[(ty4 + i) * PS_STRIDE + tx * 4] = pv;  // conflict-free
        }
        __syncthreads();

        // ---- O += P @ V  (thread: rows ty4..ty4+3, cols tx*8..tx*8+7) ----
        for (int t4 = 0; t4 < BN / 4; ++t4) {
            F4 p[4];
            #pragma unroll
            for (int i = 0; i < 4; i++)
                p[i] = ldf4(&Ps[(ty4 + i) * PS_STRIDE + t4 * 4]);  // broadcast
            #pragma unroll
            for (int tt = 0; tt < 4; tt++) {
                const float* vrow = &Vs[(t4 * 4 + tt) * VS_STRIDE + tx * 8];
                F4 va = ldf4(vrow);
                F4 vb = ldf4(vrow + 4);
                #pragma unroll
                for (int i = 0; i < 4; i++) {
                    float pi = p[i].f[tt];
                    o[i][0] += pi * va.f[0];
                    o[i][1] += pi * va.f[1];
                    o[i][2] += pi * va.f[2];
                    o[i][3] += pi * va.f[3];
                    o[i][4] += pi * vb.f[0];
                    o[i][5] += pi * vb.f[1];
                    o[i][6] += pi * vb.f[2];
                    o[i][7] += pi * vb.f[3];
                }
            }
        }
        __syncthreads();
    }

    // ---- Epilogue: O / l, store coalesced ----
    #pragma unroll
    for (int i = 0; i < 4; i++) {
        float inv = 1.0f / lrow[i];
        float* orow = Og + (size_t)(ty4 + i) * Dq + tx * 8;
        float4 u, w;
        u.x = o[i][0] * inv; u.y = o[i][1] * inv;
        u.z = o[i][2] * inv; u.w = o[i][3] * inv;
        w.x = o[i][4] * inv; w.y = o[i][5] * inv;
        w.z = o[i][6] * inv; w.w = o[i][7] * inv;
        *(float4*)orow       = u;
        *(float4*)(orow + 4) = w;
    }
}

extern "C" void kernel_launch(void* const* d_in, const int* in_sizes, int n_in,
                              void* d_out, int out_size)
{
    const float* q     = (const float*)d_in[0];
    const float* k     = (const float*)d_in[1];
    const float* v     = (const float*)d_in[2];
    const float* scale = (const float*)d_in[3];
    float* out = (float*)d_out;

    const int smem_bytes = SMEM_FLOATS * (int)sizeof(float);
    cudaFuncSetAttribute(attn_fp32_kernel,
                         cudaFuncAttributeMaxDynamicSharedMemorySize, smem_bytes);

    dim3 grid(Sq / BM, Bq * Hq);
    attn_fp32_kernel<<<grid, NTHREADS, smem_bytes>>>(q, k, v, scale, out);
}

// round 2
// speedup vs baseline: 1.5895x; 1.5895x over previous
#include <cuda_runtime.h>

// Problem constants
#define Bq 4
#define Hq 16
#define Sq 2048
#define Dq 128

// Tiling: 128x128 flash tile, 256 threads, 8x8 register microtile per thread
#define BM 128
#define BN 128
#define NT 256
#define QS 132                     // smem row stride (floats), float4-aligned
#define SMEM_FLOATS (3 * 128 * QS) // Qs + KV(shared) + Ps

#define LOG2E 1.44269504088896340736f

typedef unsigned long long u64;

struct F4 { float f[4]; };

static __device__ __forceinline__ F4 ldf4(const float* p) {
    float4 t = *(const float4*)p;
    F4 r; r.f[0] = t.x; r.f[1] = t.y; r.f[2] = t.z; r.f[3] = t.w;
    return r;
}

// Packed dual-FMA: d = a*b + c (elementwise on 2 floats). Only reachable via PTX.
static __device__ __forceinline__ float2 ffma2(float2 a, float2 b, float2 c) {
    float2 d;
    asm("fma.rn.f32x2 %0, %1, %2, %3;"
        : "=l"(reinterpret_cast<u64&>(d))
        : "l"(reinterpret_cast<u64&>(a)),
          "l"(reinterpret_cast<u64&>(b)),
          "l"(reinterpret_cast<u64&>(c)));
    return d;
}
static __device__ __forceinline__ float2 fmul2(float2 a, float2 b) {
    float2 d;
    asm("mul.rn.f32x2 %0, %1, %2;"
        : "=l"(reinterpret_cast<u64&>(d))
        : "l"(reinterpret_cast<u64&>(a)),
          "l"(reinterpret_cast<u64&>(b)));
    return d;
}
static __device__ __forceinline__ float ex2(float x) {
    float y;
    asm("ex2.approx.f32 %0, %1;" : "=f"(y) : "f"(x));
    return y;
}

__global__ __launch_bounds__(NT, 1)
void attn_fp32x2_kernel(const float* __restrict__ q,
                        const float* __restrict__ k,
                        const float* __restrict__ v,
                        const float* __restrict__ scale,
                        float* __restrict__ out)
{
    extern __shared__ float sm[];
    float* Qs  = sm;                 // [128][QS]  Q tile
    float* KVs = sm + 128 * QS;      // K^T [k][t] then V [t][d] (reused buffer)
    float* Ps  = sm + 2 * 128 * QS;  // [128][QS]  P tile

    const int tid = threadIdx.x;
    const int tx  = tid & 15;        // column group
    const int ty  = tid >> 4;        // row group; thread rows = ty + 16*i

    const int tile = blockIdx.x;     // 0..15
    const int bh   = blockIdx.y;     // 0..63

    const size_t base = (size_t)bh * Sq * Dq;
    const float* Qg = q + base + (size_t)tile * BM * Dq;
    float*       Og = out + base + (size_t)tile * BM * Dq;
    const float  scL = scale[bh] * LOG2E;   // work in log2 domain

    // ---- Load Q tile (coalesced) ----
    #pragma unroll
    for (int c = tid; c < BM * Dq / 4; c += NT) {
        int r = c >> 5, k4 = c & 31;
        float4 g = *(const float4*)(Qg + (size_t)r * Dq + k4 * 4);
        *(float4*)&Qs[r * QS + k4 * 4] = g;
    }

    // ---- State ----
    float2 o[8][4];                   // O rows ty+16i, cols {tx*4..+3, 64+tx*4..+3}
    float  mrow[8], lrow[8];
    const float NEG_INF = __int_as_float(0xff800000);
    #pragma unroll
    for (int i = 0; i < 8; i++) {
        mrow[i] = NEG_INF; lrow[i] = 0.f;
        #pragma unroll
        for (int j = 0; j < 4; j++) o[i][j] = make_float2(0.f, 0.f);
    }

    for (int n = 0; n < Sq / BN; ++n) {
        // ---- Load K transposed into KVs[k][t] (conflict-free STS) ----
        const float* Kg = k + base + (size_t)n * BN * Dq;
        #pragma unroll
        for (int c = tid; c < BN * Dq / 4; c += NT) {
            int t = c & 127, k4 = c >> 7;
            float4 g = *(const float4*)(Kg + (size_t)t * Dq + k4 * 4);
            KVs[(k4 * 4 + 0) * QS + t] = g.x;
            KVs[(k4 * 4 + 1) * QS + t] = g.y;
            KVs[(k4 * 4 + 2) * QS + t] = g.z;
            KVs[(k4 * 4 + 3) * QS + t] = g.w;
        }
        __syncthreads();

        // ---- S = Q @ K^T : 8x8 microtile, packed f32x2 on column pairs ----
        float2 acc[8][4];
        #pragma unroll
        for (int i = 0; i < 8; i++)
            #pragma unroll
            for (int j = 0; j < 4; j++) acc[i][j] = make_float2(0.f, 0.f);

        #pragma unroll 2
        for (int k4 = 0; k4 < Dq / 4; ++k4) {
            F4 a4[8];
            #pragma unroll
            for (int i = 0; i < 8; i++)
                a4[i] = ldf4(&Qs[(ty + 16 * i) * QS + k4 * 4]);   // 1-wavefront broadcast
            #pragma unroll
            for (int kk = 0; kk < 4; kk++) {
                int kr = k4 * 4 + kk;
                F4 bA = ldf4(&KVs[kr * QS + tx * 4]);            // 2-wavefront, no conflicts
                F4 bB = ldf4(&KVs[kr * QS + 64 + tx * 4]);
                float2 bA0 = make_float2(bA.f[0], bA.f[1]);
                float2 bA1 = make_float2(bA.f[2], bA.f[3]);
                float2 bB0 = make_float2(bB.f[0], bB.f[1]);
                float2 bB1 = make_float2(bB.f[2], bB.f[3]);
                #pragma unroll
                for (int i = 0; i < 8; i++) {
                    float2 as = make_float2(a4[i].f[kk], a4[i].f[kk]);
                    acc[i][0] = ffma2(as, bA0, acc[i][0]);
                    acc[i][1] = ffma2(as, bA1, acc[i][1]);
                    acc[i][2] = ffma2(as, bB0, acc[i][2]);
                    acc[i][3] = ffma2(as, bB1, acc[i][3]);
                }
            }
        }

        // ---- Online softmax (log2 domain), write P tile ----
        #pragma unroll
        for (int i = 0; i < 8; i++) {
            float z[8];
            #pragma unroll
            for (int j = 0; j < 4; j++) {
                z[2 * j + 0] = acc[i][j].x * scL;
                z[2 * j + 1] = acc[i][j].y * scL;
            }
            float rmax = z[0];
            #pragma unroll
            for (int j = 1; j < 8; j++) rmax = fmaxf(rmax, z[j]);
            #pragma unroll
            for (int off = 8; off; off >>= 1)
                rmax = fmaxf(rmax, __shfl_xor_sync(0xffffffffu, rmax, off));
            float mnew = fmaxf(mrow[i], rmax);

            float p[8], rsum = 0.f;
            #pragma unroll
            for (int j = 0; j < 8; j++) { p[j] = ex2(z[j] - mnew); rsum += p[j]; }
            #pragma unroll
            for (int off = 8; off; off >>= 1)
                rsum += __shfl_xor_sync(0xffffffffu, rsum, off);

            float alpha = ex2(mrow[i] - mnew);
            mrow[i] = mnew;
            lrow[i] = lrow[i] * alpha + rsum;
            float2 al = make_float2(alpha, alpha);
            #pragma unroll
            for (int j = 0; j < 4; j++) o[i][j] = fmul2(o[i][j], al);

            float4 pa, pb;
            pa.x = p[0]; pa.y = p[1]; pa.z = p[2]; pa.w = p[3];
            pb.x = p[4]; pb.y = p[5]; pb.z = p[6]; pb.w = p[7];
            *(float4*)&Ps[(ty + 16 * i) * QS + tx * 4]      = pa;
            *(float4*)&Ps[(ty + 16 * i) * QS + 64 + tx * 4] = pb;
        }
        __syncthreads();   // all P written, all K reads done -> KVs reusable

        // ---- Load V into KVs[t][d] (coalesced) ----
        const float* Vg = v + base + (size_t)n * BN * Dq;
        #pragma unroll
        for (int c = tid; c < BN * Dq / 4; c += NT) {
            int t = c >> 5, c4 = c & 31;
            float4 g = *(const float4*)(Vg + (size_t)t * Dq + c4 * 4);
            *(float4*)&KVs[t * QS + c4 * 4] = g;
        }
        __syncthreads();

        // ---- O += P @ V : same microtile structure ----
        #pragma unroll 2
        for (int t4 = 0; t4 < BN / 4; ++t4) {
            F4 p4[8];
            #pragma unroll
            for (int i = 0; i < 8; i++)
                p4[i] = ldf4(&Ps[(ty + 16 * i) * QS + t4 * 4]);  // broadcast
            #pragma unroll
            for (int tt = 0; tt < 4; tt++) {
                int t = t4 * 4 + tt;
                F4 vA = ldf4(&KVs[t * QS + tx * 4]);
                F4 vB = ldf4(&KVs[t * QS + 64 + tx * 4]);
                float2 vA0 = make_float2(vA.f[0], vA.f[1]);
                float2 vA1 = make_float2(vA.f[2], vA.f[3]);
                float2 vB0 = make_float2(vB.f[0], vB.f[1]);
                float2 vB1 = make_float2(vB.f[2], vB.f[3]);
                #pragma unroll
                for (int i = 0; i < 8; i++) {
                    float2 ps = make_float2(p4[i].f[tt], p4[i].f[tt]);
                    o[i][0] = ffma2(ps, vA0, o[i][0]);
                    o[i][1] = ffma2(ps, vA1, o[i][1]);
                    o[i][2] = ffma2(ps, vB0, o[i][2]);
                    o[i][3] = ffma2(ps, vB1, o[i][3]);
                }
            }
        }
        __syncthreads();   // before next tile overwrites KVs
    }

    // ---- Epilogue: normalize and store ----
    #pragma unroll
    for (int i = 0; i < 8; i++) {
        float inv = 1.0f / lrow[i];
        float2 iv = make_float2(inv, inv);
        float2 r0 = fmul2(o[i][0], iv), r1 = fmul2(o[i][1], iv);
        float2 r2 = fmul2(o[i][2], iv), r3 = fmul2(o[i][3], iv);
        float* orow = Og + (size_t)(ty + 16 * i) * Dq;
        float4 u; u.x = r0.x; u.y = r0.y; u.z = r1.x; u.w = r1.y;
        float4 w; w.x = r2.x; w.y = r2.y; w.z = r3.x; w.w = r3.y;
        *(float4*)(orow + tx * 4)      = u;
        *(float4*)(orow + 64 + tx * 4) = w;
    }
}

extern "C" void kernel_launch(void* const* d_in, const int* in_sizes, int n_in,
                              void* d_out, int out_size)
{
    const float* q     = (const float*)d_in[0];
    const float* k     = (const float*)d_in[1];
    const float* v     = (const float*)d_in[2];
    const float* scale = (const float*)d_in[3];
    float* out = (float*)d_out;

    const int smem_bytes = SMEM_FLOATS * (int)sizeof(float);
    cudaFuncSetAttribute(attn_fp32x2_kernel,
                         cudaFuncAttributeMaxDynamicSharedMemorySize, smem_bytes);

    dim3 grid(Sq / BM, Bq * Hq);
    attn_fp32x2_kernel<<<grid, NT, smem_bytes>>>(q, k, v, scale, out);
}